// round 12
// baseline (speedup 1.0000x reference)
#include <cuda_runtime.h>
#include <cuda_bf16.h>
#include <math.h>

#define H      1024
#define H4     256          // H/4
#define VOUT   32000
#define ML     128
#define ATT    129          // ML + 1
#define ATTP   160          // padded attention length (multiple of 32)
#define GRID   148
#define BLOCK  512
#define WPB    (BLOCK/32)   // 16 warps per block
#define NWARPS (GRID*WPB)   // 2368
#define MAXSLOT 14          // max rows per warp
#define ROWB   2048         // bytes per bf16 weight row
#define DSMEM  (3 * WPB * ROWB)   // 96KB: 3-stage cp.async pipeline buffer
// logits slots 0..7 (38.9MB) stay L2-resident; slots 8..13 (26.7MB) stream
// from DRAM with an evict-first L2 policy.

// ---------------- device scratch (static, no allocation) ----------------
__device__ float g_h[2][H];
__device__ float g_enc_T[(size_t)H * ATTP];    // transposed encoder outputs [j][t]
__device__ float g_M[(size_t)H * ATTP];        // M[i][t] = dot(W2[i], enc_out[t])
__device__ float g_attn[ATT];
__device__ float g_comb[H];
__device__ float g_logits[VOUT];
__device__ unsigned long long g_ptop[GRID][4]; // per-CTA top-4 packed (bf16-based)
__device__ float g_psum[GRID];                 // per-CTA sumexp wrt its own max
__device__ int g_tok;
__device__ __nv_bfloat16 g_wbf[(size_t)VOUT * H];  // 64MB bf16 copy of out_W

__device__ unsigned g_bar_count = 0;
__device__ unsigned g_bar_gen   = 0;

// ---------------- helpers ----------------
__device__ __forceinline__ float wredsum(float v) {
#pragma unroll
    for (int o = 16; o > 0; o >>= 1) v += __shfl_xor_sync(0xffffffffu, v, o);
    return v;
}
__device__ __forceinline__ float wredmax(float v) {
#pragma unroll
    for (int o = 16; o > 0; o >>= 1) v = fmaxf(v, __shfl_xor_sync(0xffffffffu, v, o));
    return v;
}
__device__ __forceinline__ unsigned long long wredmaxu64(unsigned long long v) {
#pragma unroll
    for (int o = 16; o > 0; o >>= 1) {
        unsigned long long q = __shfl_xor_sync(0xffffffffu, v, o);
        if (q > v) v = q;
    }
    return v;
}

__device__ __forceinline__ unsigned long long packf(float v, int idx) {
    unsigned u = __float_as_uint(v);
    u = (u & 0x80000000u) ? ~u : (u | 0x80000000u);   // totally ordered float bits
    return ((unsigned long long)u << 32) | (unsigned)(~(unsigned)idx); // tie -> lowest idx
}
__device__ __forceinline__ float unpack_max(unsigned long long p) {
    unsigned u = (unsigned)(p >> 32);
    unsigned b = (u & 0x80000000u) ? (u & 0x7fffffffu) : ~u;
    return __uint_as_float(b);
}
__device__ __forceinline__ int unpack_idx(unsigned long long p) {
    return (int)(~(unsigned)(p & 0xffffffffu));
}

__device__ __forceinline__ float dot4(float4 a, float4 b) {
    return a.x * b.x + a.y * b.y + a.z * b.z + a.w * b.w;
}

// 8-elem bf16 dot against two float4 halves
__device__ __forceinline__ float bfdot8(uint4 w, float4 a, float4 b) {
    float2 p0 = __bfloat1622float2(*(__nv_bfloat162*)&w.x);
    float2 p1 = __bfloat1622float2(*(__nv_bfloat162*)&w.y);
    float2 p2 = __bfloat1622float2(*(__nv_bfloat162*)&w.z);
    float2 p3 = __bfloat1622float2(*(__nv_bfloat162*)&w.w);
    return p0.x*a.x + p0.y*a.y + p1.x*a.z + p1.y*a.w
         + p2.x*b.x + p2.y*b.y + p3.x*b.z + p3.y*b.w;
}

// insert p into descending top-4 (c0>=c1>=c2>=c3)
__device__ __forceinline__ void top4_ins(unsigned long long& c0, unsigned long long& c1,
                                         unsigned long long& c2, unsigned long long& c3,
                                         unsigned long long p) {
    if (p > c0)      { c3 = c2; c2 = c1; c1 = c0; c0 = p; }
    else if (p > c1) { c3 = c2; c2 = c1; c1 = p; }
    else if (p > c2) { c3 = c2; c2 = p; }
    else if (p > c3) { c3 = p; }
}

// ---------------- grid-wide barrier (CG grid.sync pattern) ----------------
__device__ __forceinline__ unsigned ld_acq(unsigned* p) {
    unsigned v;
    asm volatile("ld.acquire.gpu.u32 %0, [%1];" : "=r"(v) : "l"(p) : "memory");
    return v;
}
__device__ __forceinline__ void st_rel(unsigned* p, unsigned v) {
    asm volatile("st.release.gpu.u32 [%0], %1;" :: "l"(p), "r"(v) : "memory");
}

__device__ __forceinline__ void gsync() {
    __syncthreads();
    if (threadIdx.x == 0) {
        unsigned gen = ld_acq(&g_bar_gen);
        __threadfence();
        if (atomicAdd(&g_bar_count, 1) == GRID - 1) {
            g_bar_count = 0;
            st_rel(&g_bar_gen, gen + 1);
        } else {
            while (ld_acq(&g_bar_gen) == gen) { }
        }
    }
    __syncthreads();
}

// ---------------- cp.async primitives ----------------
__device__ __forceinline__ unsigned smem_u32(const void* p) {
    return (unsigned)__cvta_generic_to_shared(p);
}
__device__ __forceinline__ void cp16(unsigned dst, const void* src) {
    asm volatile("cp.async.cg.shared.global [%0], [%1], 16;"
                 :: "r"(dst), "l"(src));
}
__device__ __forceinline__ void cp16_ev(unsigned dst, const void* src,
                                        unsigned long long pol) {
    asm volatile("cp.async.cg.shared.global.L2::cache_hint [%0], [%1], 16, %2;"
                 :: "r"(dst), "l"(src), "l"(pol));
}
__device__ __forceinline__ void cp_commit() {
    asm volatile("cp.async.commit_group;" ::: "memory");
}
__device__ __forceinline__ void cp_wait2() {
    asm volatile("cp.async.wait_group 2;" ::: "memory");
}

// ---------------- shared-memory layout ----------------
struct Smem {
    float e[ATTP];                // attention softmax weights (zero-padded)
    float slot[WPB * MAXSLOT];    // raw logits per warp slot
    float red[WPB];               // warp-level reduction scratch
    float gh[8][4];               // parked Whh@h gate sums (row-warp exchange)
    unsigned long long wtop[WPB][4];
    unsigned long long top4[4];
    unsigned long long cand[4];
    float bf[4];                  // scalar broadcasts
    unsigned long long bu;
};

// ---------------- phases ----------------

// Encoder GRU step, warp-pair split: warps 0..6 x-side (Wih), warps 8..14
// h-side (Whh), combined via smem + one __syncthreads.
__device__ __forceinline__ void gru_phase_enc(
    const float* __restrict__ Wih, const float* __restrict__ Whh,
    const float* __restrict__ bih, const float* __restrict__ bhh,
    const float* __restrict__ x, const float* __restrict__ h,
    float* __restrict__ ho, int t, Smem* sm)
{
    int wib = threadIdx.x >> 5;
    int lane = threadIdx.x & 31;
    int wp = wib & 7;
    bool xs = (wib < 7);
    bool hs = (wib >= 8 && wib < 15);
    int row = wp * GRID + (int)blockIdx.x;
    bool act = (xs || hs) && row < H;

    float a0 = 0.f, a1 = 0.f, a2 = 0.f;
    if (act) {
        const float*  W  = xs ? Wih : Whh;
        const float4* v4 = (const float4*)(xs ? x : h);
        const float4* W0 = (const float4*)(W + (size_t)row * H);
        const float4* W1 = (const float4*)(W + (size_t)(row + H) * H);
        const float4* W2 = (const float4*)(W + (size_t)(row + 2 * H) * H);
#pragma unroll 4
        for (int k = lane; k < H4; k += 32) {
            float4 vv = v4[k];
            a0 += dot4(W0[k], vv);
            a1 += dot4(W1[k], vv);
            a2 += dot4(W2[k], vv);
        }
        a0 = wredsum(a0); a1 = wredsum(a1); a2 = wredsum(a2);
        if (hs && lane == 0) {
            sm->gh[wp][0] = a0 + bhh[row];
            sm->gh[wp][1] = a1 + bhh[row + H];
            sm->gh[wp][2] = a2 + bhh[row + 2 * H];
        }
    }
    __syncthreads();
    if (act && xs && lane == 0) {
        float ir  = a0 + bih[row];
        float iz  = a1 + bih[row + H];
        float inn = a2 + bih[row + 2 * H];
        float hr = sm->gh[wp][0];
        float hz = sm->gh[wp][1];
        float hn = sm->gh[wp][2];
        float r = 1.f / (1.f + expf(-(ir + hr)));
        float z = 1.f / (1.f + expf(-(iz + hz)));
        float n = tanhf(inn + r * hn);
        float hnew = (1.f - z) * n + z * h[row];
        ho[row] = hnew;
        g_enc_T[(size_t)row * ATTP + t] = hnew;  // transposed store
    }
}

// one-time after encoder: M[i][t] = dot(comb_W[i, H:2H], enc_out[t])
__device__ __forceinline__ void build_M(const float* __restrict__ comb_W)
{
    int wib = threadIdx.x >> 5;
    int lane = threadIdx.x & 31;
    if (wib >= 7) return;
    int row = wib * GRID + (int)blockIdx.x;
    if (row >= H) return;

    const float4* W2 = (const float4*)(comb_W + (size_t)row * 2 * H + H);
    float a0 = 0.f, a1 = 0.f, a2 = 0.f, a3 = 0.f, a4 = 0.f;
#pragma unroll 2
    for (int j4 = 0; j4 < H4; j4++) {
        float4 w = W2[j4];
        const float* E = g_enc_T + (size_t)(j4 * 4) * ATTP + lane;
#pragma unroll
        for (int c = 0; c < 4; c++) {
            float wc = (c == 0) ? w.x : (c == 1) ? w.y : (c == 2) ? w.z : w.w;
            const float* Ec = E + (size_t)c * ATTP;
            a0 += wc * Ec[0];
            a1 += wc * Ec[32];
            a2 += wc * Ec[64];
            a3 += wc * Ec[96];
            a4 += wc * Ec[128];
        }
    }
    float* Mr = g_M + (size_t)row * ATTP;
    Mr[lane]       = a0;
    Mr[lane + 32]  = a1;
    Mr[lane + 64]  = a2;
    Mr[lane + 96]  = a3;
    Mr[lane + 128] = a4;
}

// decoder phase A: comb rows (w0-6) + softmax (w15) + Whh@hc dots (w8-14,
// parked in smem for the next phase).
__device__ __forceinline__ void comb_whh_phase(
    const float* __restrict__ comb_W, const float* __restrict__ comb_b,
    const float* __restrict__ dec_emb,
    const float* __restrict__ dec_Whh, const float* __restrict__ dec_bhh,
    const float* __restrict__ hc, Smem* sm)
{
    int wib = threadIdx.x >> 5;
    int lane = threadIdx.x & 31;
    int tok = g_tok;

    if (wib == 15) {   // local softmax of the 129 attention logits
        float v[5];
        float mx = -INFINITY;
#pragma unroll
        for (int k = 0; k < 5; k++) {
            int idx = lane + 32 * k;
            v[k] = (idx < ATT) ? g_attn[idx] : -INFINITY;
            mx = fmaxf(mx, v[k]);
        }
        mx = wredmax(mx);
        float s = 0.f;
#pragma unroll
        for (int k = 0; k < 5; k++) {
            int idx = lane + 32 * k;
            float e = (idx < ATT) ? expf(v[k] - mx) : 0.f;
            sm->e[idx] = e;        // idx < 160 always; pads are zero
            s += e;
        }
        s = wredsum(s);
        if (lane == 0) sm->bf[0] = 1.f / s;
    }

    // warps 8..14: Whh@hc gate sums parked in smem
    if (wib >= 8 && wib < 15) {
        int wp = wib - 8;
        int row = wp * GRID + (int)blockIdx.x;
        if (row < H) {
            const float4* h4 = (const float4*)hc;
            const float4* W0 = (const float4*)(dec_Whh + (size_t)row * H);
            const float4* W1 = (const float4*)(dec_Whh + (size_t)(row + H) * H);
            const float4* W2 = (const float4*)(dec_Whh + (size_t)(row + 2 * H) * H);
            float hr = 0.f, hz = 0.f, hn = 0.f;
#pragma unroll 4
            for (int k = lane; k < H4; k += 32) {
                float4 hv = h4[k];
                hr += dot4(W0[k], hv);
                hz += dot4(W1[k], hv);
                hn += dot4(W2[k], hv);
            }
            hr = wredsum(hr); hz = wredsum(hz); hn = wredsum(hn);
            if (lane == 0) {
                sm->gh[wp][0] = hr + dec_bhh[row];
                sm->gh[wp][1] = hz + dec_bhh[row + H];
                sm->gh[wp][2] = hn + dec_bhh[row + 2 * H];
            }
        }
    }

    int row = wib * GRID + (int)blockIdx.x;
    bool act = (wib < 7) && (row < H);
    float a = 0.f;
    if (act) {
        const float4* W  = (const float4*)(comb_W + (size_t)row * 2 * H);
        const float4* e4 = (const float4*)(dec_emb + (size_t)tok * H);
#pragma unroll 8
        for (int k = lane; k < H4; k += 32) a += dot4(W[k], e4[k]);
    }
    __syncthreads();
    if (act) {
        const float* Mr = g_M + (size_t)row * ATTP;
        float b = 0.f;
#pragma unroll
        for (int k = 0; k < 5; k++) {
            int t = lane + 32 * k;
            b += sm->e[t] * Mr[t];   // pads contribute 0
        }
        float tot = a + b * sm->bf[0];
        tot = wredsum(tot);
        if (lane == 0) g_comb[row] = fmaxf(tot + comb_b[row], 0.f);
    }
}

// decoder phase B: finish GRU — Wih@comb dots + gate math using parked Whh sums.
__device__ __forceinline__ void gru_fin_phase(
    const float* __restrict__ dec_Wih, const float* __restrict__ dec_bih,
    const float* __restrict__ hc, float* __restrict__ hn_out, Smem* sm)
{
    int wib = threadIdx.x >> 5;
    int lane = threadIdx.x & 31;
    if (wib >= 7) return;
    int row = wib * GRID + (int)blockIdx.x;
    if (row >= H) return;

    const float4* x4 = (const float4*)g_comb;
    const float4* W0 = (const float4*)(dec_Wih + (size_t)row * H);
    const float4* W1 = (const float4*)(dec_Wih + (size_t)(row + H) * H);
    const float4* W2 = (const float4*)(dec_Wih + (size_t)(row + 2 * H) * H);
    float ir = 0.f, iz = 0.f, inn = 0.f;
#pragma unroll 4
    for (int k = lane; k < H4; k += 32) {
        float4 xv = x4[k];
        ir  += dot4(W0[k], xv);
        iz  += dot4(W1[k], xv);
        inn += dot4(W2[k], xv);
    }
    ir = wredsum(ir); iz = wredsum(iz); inn = wredsum(inn);
    if (lane == 0) {
        ir  += dec_bih[row];
        iz  += dec_bih[row + H];
        inn += dec_bih[row + 2 * H];
        float hr = sm->gh[wib][0];
        float hz = sm->gh[wib][1];
        float hn = sm->gh[wib][2];
        float r = 1.f / (1.f + expf(-(ir + hr)));
        float z = 1.f / (1.f + expf(-(iz + hz)));
        float n = tanhf(inn + r * hn);
        hn_out[row] = (1.f - z) * n + z * hc[row];
    }
}

// logits GEMV: cp.async 3-stage pipeline through smem (register-free loads,
// 2 rows always in flight per warp). Resident slots (0..7) use default L2
// caching; streamed slots (8..13) use evict-first policy. Math identical to
// the register version.
__device__ __forceinline__ void logits_phase(
    const float* __restrict__ out_b, const float* __restrict__ h,
    Smem* sm, char* dyn)
{
    int tid = threadIdx.x, lane = tid & 31, wib = tid >> 5;
    int gw = (int)blockIdx.x * WPB + wib;

    if (tid < WPB * MAXSLOT) sm->slot[tid] = -INFINITY;
    __syncthreads();

    const float4* h4 = (const float4*)h;
    float4 hv[8];
#pragma unroll
    for (int i = 0; i < 4; i++) {
        hv[2*i]   = h4[(lane + 32*i) * 2];
        hv[2*i+1] = h4[(lane + 32*i) * 2 + 1];
    }
    float* slotp = sm->slot + wib * MAXSLOT;

    unsigned long long pol;
    asm volatile("createpolicy.fractional.L2::evict_first.b64 %0, 1.0;" : "=l"(pol));

    // processing order interleaves resident (0..7) and streamed (8..13) slots
    const int ORD[MAXSLOT] = {0, 8, 1, 9, 2, 10, 3, 11, 4, 12, 5, 13, 6, 7};

    // stage base smem addresses for this warp
    unsigned sbase[3];
#pragma unroll
    for (int s = 0; s < 3; s++)
        sbase[s] = smem_u32(dyn + ((size_t)s * WPB + wib) * ROWB);

    // prefetch helper (inlined): slot n -> stage st
    auto prefetch = [&](int n, int st) {
        int r = gw + n * NWARPS;
        if (r >= VOUT) r = gw;                 // clamp (slot 13 OOB warps)
        const char* src = (const char*)(g_wbf + (size_t)r * H);
        bool ev = (n >= 8);
#pragma unroll
        for (int i = 0; i < 4; i++) {
            unsigned dst = sbase[st] + (unsigned)(lane + 32 * i) * 16;
            const void* sp = src + (size_t)(lane + 32 * i) * 16;
            if (ev) cp16_ev(dst, sp, pol);
            else    cp16(dst, sp);
        }
        cp_commit();
    };

    prefetch(ORD[0], 0);
    prefetch(ORD[1], 1);

#pragma unroll 1
    for (int k = 0; k < MAXSLOT; k++) {
        if (k + 2 < MAXSLOT) prefetch(ORD[k + 2], (k + 2) % 3);
        else cp_commit();                       // empty group keeps counting aligned
        cp_wait2();                             // group k complete

        int n = ORD[k];
        int r = gw + n * NWARPS;
        bool ok = (r < VOUT);
        const uint4* wrow = (const uint4*)(dyn + ((size_t)(k % 3) * WPB + wib) * ROWB);
        float a = 0.f;
#pragma unroll
        for (int i = 0; i < 4; i++)
            a += bfdot8(wrow[lane + 32 * i], hv[2*i], hv[2*i+1]);
        a = wredsum(a);
        if (lane == 0 && ok) {
            a += out_b[r];
            g_logits[r] = a;
            slotp[n] = a;
        }
    }

    // per-warp top-4 scan (lane0, off the hot loop)
    if (lane == 0) {
        unsigned long long c0 = 0, c1 = 0, c2 = 0, c3 = 0;
#pragma unroll
        for (int n = 0; n < MAXSLOT; n++) {
            int row = gw + n * NWARPS;
            if (row < VOUT) {
                unsigned long long p = packf(slotp[n], row);
                top4_ins(c0, c1, c2, c3, p);
            }
        }
        sm->wtop[wib][0] = c0; sm->wtop[wib][1] = c1;
        sm->wtop[wib][2] = c2; sm->wtop[wib][3] = c3;
    }
    __syncthreads();

    // warp0: pop-merge 16 warp lists -> CTA top-4
    if (wib == 0) {
        unsigned long long a0 = 0, a1 = 0, a2 = 0, a3 = 0;
        if (lane < WPB) {
            a0 = sm->wtop[lane][0]; a1 = sm->wtop[lane][1];
            a2 = sm->wtop[lane][2]; a3 = sm->wtop[lane][3];
        }
        int pos = 0;
        unsigned long long t[4];
#pragma unroll
        for (int k = 0; k < 4; k++) {
            unsigned long long head = (pos == 0) ? a0 : (pos == 1) ? a1 :
                                      (pos == 2) ? a2 : (pos == 3) ? a3 : 0ull;
            unsigned long long m = wredmaxu64(head);
            t[k] = m;
            if (head == m && pos < 4) pos++;
        }
        if (lane == 0) {
#pragma unroll
            for (int k = 0; k < 4; k++) g_ptop[blockIdx.x][k] = t[k];
            sm->bu = t[0];
        }
    }
    __syncthreads();

    // CTA sumexp wrt CTA max: warp-level (slots 0..223 covered by warps 0..6)
    {
        float m = unpack_max(sm->bu);
        float e = (tid < WPB * MAXSLOT) ? expf(sm->slot[tid] - m) : 0.f;
        e = wredsum(e);
        if (lane == 0) sm->red[wib] = e;
        __syncthreads();
        if (tid == 0) {
            float S = 0.f;
#pragma unroll
            for (int i = 0; i < 7; i++) S += sm->red[i];
            g_psum[blockIdx.x] = S;
        }
    }
}

// global top-4 merge + lse; fp32 recheck of top-4 for exact argmax;
// write logp row; fuse next-step attention-logit prep
__device__ __forceinline__ void out_phase(
    float* __restrict__ out, int step,
    const float* __restrict__ out_W, const float* __restrict__ out_b,
    const float* __restrict__ attn_W, const float* __restrict__ attn_b,
    const float* __restrict__ dec_emb, const float* __restrict__ h, Smem* sm)
{
    int tid = threadIdx.x, lane = tid & 31, wib = tid >> 5;

    if (wib == 0) {
        unsigned long long c0 = 0, c1 = 0, c2 = 0, c3 = 0;
        for (int cc = lane; cc < GRID; cc += 32) {
#pragma unroll
            for (int k = 0; k < 4; k++)
                top4_ins(c0, c1, c2, c3, g_ptop[cc][k]);
        }
        int pos = 0;
        unsigned long long t[4];
#pragma unroll
        for (int k = 0; k < 4; k++) {
            unsigned long long head = (pos == 0) ? c0 : (pos == 1) ? c1 :
                                      (pos == 2) ? c2 : (pos == 3) ? c3 : 0ull;
            unsigned long long mm = wredmaxu64(head);
            t[k] = mm;
            if (head == mm && pos < 4) pos++;
        }
        float M = unpack_max(t[0]);
        float S = 0.f;
        for (int cc = lane; cc < GRID; cc += 32)
            S += g_psum[cc] * expf(unpack_max(g_ptop[cc][0]) - M);
        S = wredsum(S);
        if (lane == 0) {
#pragma unroll
            for (int k = 0; k < 4; k++) sm->top4[k] = t[k];
            sm->bf[0] = M + logf(S);
        }
    }
    __syncthreads();
    float lse = sm->bf[0];

    int g = (int)blockIdx.x * BLOCK + tid;
    if (g < VOUT) out[(size_t)step * VOUT + g] = g_logits[g] - lse;

    // fp32 recheck of the 4 candidates (warps 0..3, one row each)
    if (wib < 4) {
        int rk = unpack_idx(sm->top4[wib]);
        const float4* W = (const float4*)(out_W + (size_t)rk * H);
        const float4* h4 = (const float4*)h;
        float a = 0.f;
#pragma unroll 4
        for (int k = lane; k < H4; k += 32) a += dot4(W[k], h4[k]);
        a = wredsum(a);
        if (lane == 0) sm->cand[wib] = packf(a + out_b[rk], rk);
    }
    __syncthreads();
    unsigned long long w = sm->cand[0];
#pragma unroll
    for (int k = 1; k < 4; k++) if (sm->cand[k] > w) w = sm->cand[k];
    int tok = unpack_idx(w);

    // next-step attention logits: two-warp split per CTA row
    if ((int)blockIdx.x < ATT) {
        int r = (int)blockIdx.x;
        if (wib == 8) {        // emb half
            const float4* W  = (const float4*)(attn_W + (size_t)r * 2 * H);
            const float4* e4 = (const float4*)(dec_emb + (size_t)tok * H);
            float a = 0.f;
#pragma unroll 4
            for (int k = lane; k < H4; k += 32) a += dot4(W[k], e4[k]);
            a = wredsum(a);
            if (lane == 0) sm->bf[1] = a;
        } else if (wib == 9) { // h half
            const float4* W  = (const float4*)(attn_W + (size_t)r * 2 * H + H);
            const float4* h4 = (const float4*)h;
            float a = 0.f;
#pragma unroll 4
            for (int k = lane; k < H4; k += 32) a += dot4(W[k], h4[k]);
            a = wredsum(a);
            if (lane == 0) sm->bf[2] = a;
        }
        __syncthreads();
        if (tid == 0) g_attn[r] = sm->bf[1] + sm->bf[2] + attn_b[r];
    }
    if (blockIdx.x == 0 && tid == 0) g_tok = tok;
}

// ---------------- the single persistent kernel ----------------
__global__ void __launch_bounds__(BLOCK, 1) k_all(
    const int* __restrict__ tokens,
    const float* __restrict__ enc_emb,
    const float* __restrict__ enc_Wih, const float* __restrict__ enc_Whh,
    const float* __restrict__ enc_bih, const float* __restrict__ enc_bhh,
    const float* __restrict__ dec_emb,
    const float* __restrict__ attn_W, const float* __restrict__ attn_b,
    const float* __restrict__ comb_W, const float* __restrict__ comb_b,
    const float* __restrict__ dec_Wih, const float* __restrict__ dec_Whh,
    const float* __restrict__ dec_bih, const float* __restrict__ dec_bhh,
    const float* __restrict__ out_W, const float* __restrict__ out_b,
    float* __restrict__ out)
{
    __shared__ Smem sm;
    extern __shared__ __align__(16) char dynbuf[];
    int tid = threadIdx.x;

    // one-time: convert out_W to bf16 (grid-stride, vectorized)
    {
        const float4* w4 = (const float4*)out_W;
        uint2* dst = (uint2*)g_wbf;
        const int n4 = VOUT * (H / 4);
        for (int i = (int)blockIdx.x * BLOCK + tid; i < n4; i += GRID * BLOCK) {
            float4 v = __ldcs(&w4[i]);
            __nv_bfloat162 lo = __floats2bfloat162_rn(v.x, v.y);
            __nv_bfloat162 hi = __floats2bfloat162_rn(v.z, v.w);
            uint2 o;
            o.x = *(unsigned*)&lo;
            o.y = *(unsigned*)&hi;
            dst[i] = o;
        }
    }

    // init: h0 = 0, zero enc_T (padding columns must be 0)
    {
        int gt = (int)blockIdx.x * BLOCK + tid;
        if (gt < H) g_h[0][gt] = 0.f;
        for (int i = gt; i < H * ATTP; i += GRID * BLOCK) g_enc_T[i] = 0.f;
    }
    gsync();

    // ---- encoder (warp-pair split, writes transposed enc_T) ----
    for (int t = 0; t < ML; t++) {
        const float* x = enc_emb + (size_t)tokens[t] * H;
        gru_phase_enc(enc_Wih, enc_Whh, enc_bih, enc_bhh, x,
                      g_h[t & 1], g_h[(t & 1) ^ 1], t, &sm);
        gsync();
    }
    // final encoder hidden in g_h[0]

    // ---- build M (warps 0..6) + decoder prep (warps 8,9) in one phase ----
    build_M(comb_W);
    if ((int)blockIdx.x < ATT) {
        int r = (int)blockIdx.x;
        int wib = tid >> 5, lane = tid & 31;
        if (wib == 8) {        // emb half (tok = SOS = 0)
            const float4* W  = (const float4*)(attn_W + (size_t)r * 2 * H);
            const float4* e4 = (const float4*)dec_emb;
            float a = 0.f;
#pragma unroll 4
            for (int k = lane; k < H4; k += 32) a += dot4(W[k], e4[k]);
            a = wredsum(a);
            if (lane == 0) sm.bf[1] = a;
        } else if (wib == 9) { // h half
            const float4* W  = (const float4*)(attn_W + (size_t)r * 2 * H + H);
            const float4* h4 = (const float4*)g_h[0];
            float a = 0.f;
#pragma unroll 4
            for (int k = lane; k < H4; k += 32) a += dot4(W[k], h4[k]);
            a = wredsum(a);
            if (lane == 0) sm.bf[2] = a;
        }
    }
    __syncthreads();
    if ((int)blockIdx.x < ATT && tid == 0)
        g_attn[blockIdx.x] = sm.bf[1] + sm.bf[2] + attn_b[blockIdx.x];
    if (blockIdx.x == 0 && tid == 0) g_tok = 0;
    gsync();

    // ---- decoder: 4 barriers per step; Whh work hidden inside comb phase ----
    for (int s = 0; s < ML; s++) {
        const float* hc = g_h[s & 1];
        float* hn = g_h[(s & 1) ^ 1];

        comb_whh_phase(comb_W, comb_b, dec_emb,
                       dec_Whh, dec_bhh, hc, &sm);             gsync();
        gru_fin_phase(dec_Wih, dec_bih, hc, hn, &sm);          gsync();
        logits_phase(out_b, hn, &sm, dynbuf);                  gsync();
        out_phase(out, s, out_W, out_b, attn_W, attn_b,
                  dec_emb, hn, &sm);                           gsync();
    }
}

// ---------------- host launcher ----------------
extern "C" void kernel_launch(void* const* d_in, const int* in_sizes, int n_in,
                              void* d_out, int out_size)
{
    const int*   tokens  = (const int*)  d_in[0];
    // d_in[1] = max_length (compile-time ML=128)
    const float* enc_emb = (const float*)d_in[2];
    const float* enc_Wih = (const float*)d_in[3];
    const float* enc_Whh = (const float*)d_in[4];
    const float* enc_bih = (const float*)d_in[5];
    const float* enc_bhh = (const float*)d_in[6];
    const float* dec_emb = (const float*)d_in[7];
    const float* attn_W  = (const float*)d_in[8];
    const float* attn_b  = (const float*)d_in[9];
    const float* comb_W  = (const float*)d_in[10];
    const float* comb_b  = (const float*)d_in[11];
    const float* dec_Wih = (const float*)d_in[12];
    const float* dec_Whh = (const float*)d_in[13];
    const float* dec_bih = (const float*)d_in[14];
    const float* dec_bhh = (const float*)d_in[15];
    const float* out_W   = (const float*)d_in[16];
    const float* out_b   = (const float*)d_in[17];
    float* out = (float*)d_out;

    static int attr_set = 0;
    if (!attr_set) {
        cudaFuncSetAttribute(k_all, cudaFuncAttributeMaxDynamicSharedMemorySize,
                             DSMEM);
        attr_set = 1;
    }

    k_all<<<GRID, BLOCK, DSMEM>>>(tokens, enc_emb, enc_Wih, enc_Whh,
                                  enc_bih, enc_bhh,
                                  dec_emb, attn_W, attn_b, comb_W, comb_b,
                                  dec_Wih, dec_Whh, dec_bih, dec_bhh,
                                  out_W, out_b, out);
}

// round 13
// speedup vs baseline: 1.1890x; 1.1890x over previous
#include <cuda_runtime.h>
#include <cuda_bf16.h>
#include <math.h>

#define H      1024
#define H4     256          // H/4
#define VOUT   32000
#define ML     128
#define ATT    129          // ML + 1
#define ATTP   160          // padded attention length (multiple of 32)
#define GRID   148
#define BLOCK  512
#define WPB    (BLOCK/32)   // 16 warps per block
#define NWARPS (GRID*WPB)   // 2368
#define MAXSLOT 14          // max rows per warp

// ---------------- device scratch (static, no allocation) ----------------
__device__ float g_h[2][H];
__device__ float g_enc_T[(size_t)H * ATTP];    // transposed encoder outputs [j][t]
__device__ float g_M[(size_t)H * ATTP];        // M[i][t] = dot(W2[i], enc_out[t])
__device__ float g_attn[ATT];
__device__ float g_comb[H];
__device__ float g_logits[VOUT];
__device__ unsigned long long g_ptop[GRID][4]; // per-CTA top-4 packed
__device__ float g_psum[GRID];                 // per-CTA sumexp wrt its own max
__device__ int g_tok;
__device__ unsigned g_wq[(size_t)VOUT * 256];  // 32MB int8 out_W (4 int8 / uint)
__device__ float g_wscale[VOUT];               // per-row dequant scale (maxabs/127)

__device__ unsigned g_bar_count = 0;
__device__ unsigned g_bar_gen   = 0;

// ---------------- helpers ----------------
__device__ __forceinline__ float wredsum(float v) {
#pragma unroll
    for (int o = 16; o > 0; o >>= 1) v += __shfl_xor_sync(0xffffffffu, v, o);
    return v;
}
__device__ __forceinline__ int wredsumi(int v) {
#pragma unroll
    for (int o = 16; o > 0; o >>= 1) v += __shfl_xor_sync(0xffffffffu, v, o);
    return v;
}
__device__ __forceinline__ float wredmax(float v) {
#pragma unroll
    for (int o = 16; o > 0; o >>= 1) v = fmaxf(v, __shfl_xor_sync(0xffffffffu, v, o));
    return v;
}
__device__ __forceinline__ unsigned long long wredmaxu64(unsigned long long v) {
#pragma unroll
    for (int o = 16; o > 0; o >>= 1) {
        unsigned long long q = __shfl_xor_sync(0xffffffffu, v, o);
        if (q > v) v = q;
    }
    return v;
}

__device__ __forceinline__ unsigned long long packf(float v, int idx) {
    unsigned u = __float_as_uint(v);
    u = (u & 0x80000000u) ? ~u : (u | 0x80000000u);   // totally ordered float bits
    return ((unsigned long long)u << 32) | (unsigned)(~(unsigned)idx); // tie -> lowest idx
}
__device__ __forceinline__ float unpack_max(unsigned long long p) {
    unsigned u = (unsigned)(p >> 32);
    unsigned b = (u & 0x80000000u) ? (u & 0x7fffffffu) : ~u;
    return __uint_as_float(b);
}
__device__ __forceinline__ int unpack_idx(unsigned long long p) {
    return (int)(~(unsigned)(p & 0xffffffffu));
}

__device__ __forceinline__ float dot4(float4 a, float4 b) {
    return a.x * b.x + a.y * b.y + a.z * b.z + a.w * b.w;
}

__device__ __forceinline__ unsigned q4(float4 v, float inv) {
    int a = __float2int_rn(v.x * inv);
    int b = __float2int_rn(v.y * inv);
    int c = __float2int_rn(v.z * inv);
    int d = __float2int_rn(v.w * inv);
    return (unsigned)(a & 0xFF) | ((unsigned)(b & 0xFF) << 8) |
           ((unsigned)(c & 0xFF) << 16) | ((unsigned)(d & 0xFF) << 24);
}

// insert p into descending top-4 (c0>=c1>=c2>=c3)
__device__ __forceinline__ void top4_ins(unsigned long long& c0, unsigned long long& c1,
                                         unsigned long long& c2, unsigned long long& c3,
                                         unsigned long long p) {
    if (p > c0)      { c3 = c2; c2 = c1; c1 = c0; c0 = p; }
    else if (p > c1) { c3 = c2; c2 = c1; c1 = p; }
    else if (p > c2) { c3 = c2; c2 = p; }
    else if (p > c3) { c3 = p; }
}

// ---------------- grid-wide barrier (CG grid.sync pattern) ----------------
__device__ __forceinline__ unsigned ld_acq(unsigned* p) {
    unsigned v;
    asm volatile("ld.acquire.gpu.u32 %0, [%1];" : "=r"(v) : "l"(p) : "memory");
    return v;
}
__device__ __forceinline__ void st_rel(unsigned* p, unsigned v) {
    asm volatile("st.release.gpu.u32 [%0], %1;" :: "l"(p), "r"(v) : "memory");
}

__device__ __forceinline__ void gsync() {
    __syncthreads();
    if (threadIdx.x == 0) {
        unsigned gen = ld_acq(&g_bar_gen);
        __threadfence();
        if (atomicAdd(&g_bar_count, 1) == GRID - 1) {
            g_bar_count = 0;
            st_rel(&g_bar_gen, gen + 1);
        } else {
            while (ld_acq(&g_bar_gen) == gen) { }
        }
    }
    __syncthreads();
}

// ---------------- shared-memory layout ----------------
struct Smem {
    float e[ATTP];                // attention softmax weights (zero-padded)
    float slot[WPB * MAXSLOT];    // raw logits per warp slot
    float red[WPB];               // warp-level reduction scratch
    float gh[8][4];               // parked Whh@h gate sums (row-warp exchange)
    unsigned hq[256];             // quantized h (4 int8 per uint)
    unsigned long long wtop[WPB][4];
    unsigned long long top4[4];
    unsigned long long cand[4];
    float bf[4];                  // scalar broadcasts
    unsigned long long bu;
};

// ---------------- phases ----------------

// Encoder GRU step, warp-pair split: warps 0..6 x-side (Wih), warps 8..14
// h-side (Whh), combined via smem + one __syncthreads.
__device__ __forceinline__ void gru_phase_enc(
    const float* __restrict__ Wih, const float* __restrict__ Whh,
    const float* __restrict__ bih, const float* __restrict__ bhh,
    const float* __restrict__ x, const float* __restrict__ h,
    float* __restrict__ ho, int t, Smem* sm)
{
    int wib = threadIdx.x >> 5;
    int lane = threadIdx.x & 31;
    int wp = wib & 7;
    bool xs = (wib < 7);
    bool hs = (wib >= 8 && wib < 15);
    int row = wp * GRID + (int)blockIdx.x;
    bool act = (xs || hs) && row < H;

    float a0 = 0.f, a1 = 0.f, a2 = 0.f;
    if (act) {
        const float*  W  = xs ? Wih : Whh;
        const float4* v4 = (const float4*)(xs ? x : h);
        const float4* W0 = (const float4*)(W + (size_t)row * H);
        const float4* W1 = (const float4*)(W + (size_t)(row + H) * H);
        const float4* W2 = (const float4*)(W + (size_t)(row + 2 * H) * H);
#pragma unroll 4
        for (int k = lane; k < H4; k += 32) {
            float4 vv = v4[k];
            a0 += dot4(W0[k], vv);
            a1 += dot4(W1[k], vv);
            a2 += dot4(W2[k], vv);
        }
        a0 = wredsum(a0); a1 = wredsum(a1); a2 = wredsum(a2);
        if (hs && lane == 0) {
            sm->gh[wp][0] = a0 + bhh[row];
            sm->gh[wp][1] = a1 + bhh[row + H];
            sm->gh[wp][2] = a2 + bhh[row + 2 * H];
        }
    }
    __syncthreads();
    if (act && xs && lane == 0) {
        float ir  = a0 + bih[row];
        float iz  = a1 + bih[row + H];
        float inn = a2 + bih[row + 2 * H];
        float hr = sm->gh[wp][0];
        float hz = sm->gh[wp][1];
        float hn = sm->gh[wp][2];
        float r = 1.f / (1.f + expf(-(ir + hr)));
        float z = 1.f / (1.f + expf(-(iz + hz)));
        float n = tanhf(inn + r * hn);
        float hnew = (1.f - z) * n + z * h[row];
        ho[row] = hnew;
        g_enc_T[(size_t)row * ATTP + t] = hnew;  // transposed store
    }
}

// one-time after encoder: M[i][t] = dot(comb_W[i, H:2H], enc_out[t])
__device__ __forceinline__ void build_M(const float* __restrict__ comb_W)
{
    int wib = threadIdx.x >> 5;
    int lane = threadIdx.x & 31;
    if (wib >= 7) return;
    int row = wib * GRID + (int)blockIdx.x;
    if (row >= H) return;

    const float4* W2 = (const float4*)(comb_W + (size_t)row * 2 * H + H);
    float a0 = 0.f, a1 = 0.f, a2 = 0.f, a3 = 0.f, a4 = 0.f;
#pragma unroll 2
    for (int j4 = 0; j4 < H4; j4++) {
        float4 w = W2[j4];
        const float* E = g_enc_T + (size_t)(j4 * 4) * ATTP + lane;
#pragma unroll
        for (int c = 0; c < 4; c++) {
            float wc = (c == 0) ? w.x : (c == 1) ? w.y : (c == 2) ? w.z : w.w;
            const float* Ec = E + (size_t)c * ATTP;
            a0 += wc * Ec[0];
            a1 += wc * Ec[32];
            a2 += wc * Ec[64];
            a3 += wc * Ec[96];
            a4 += wc * Ec[128];
        }
    }
    float* Mr = g_M + (size_t)row * ATTP;
    Mr[lane]       = a0;
    Mr[lane + 32]  = a1;
    Mr[lane + 64]  = a2;
    Mr[lane + 96]  = a3;
    Mr[lane + 128] = a4;
}

// decoder phase A: comb rows (w0-6) + softmax (w15) + Whh@hc dots (w8-14).
__device__ __forceinline__ void comb_whh_phase(
    const float* __restrict__ comb_W, const float* __restrict__ comb_b,
    const float* __restrict__ dec_emb,
    const float* __restrict__ dec_Whh, const float* __restrict__ dec_bhh,
    const float* __restrict__ hc, Smem* sm)
{
    int wib = threadIdx.x >> 5;
    int lane = threadIdx.x & 31;
    int tok = g_tok;

    if (wib == 15) {   // local softmax of the 129 attention logits
        float v[5];
        float mx = -INFINITY;
#pragma unroll
        for (int k = 0; k < 5; k++) {
            int idx = lane + 32 * k;
            v[k] = (idx < ATT) ? g_attn[idx] : -INFINITY;
            mx = fmaxf(mx, v[k]);
        }
        mx = wredmax(mx);
        float s = 0.f;
#pragma unroll
        for (int k = 0; k < 5; k++) {
            int idx = lane + 32 * k;
            float e = (idx < ATT) ? expf(v[k] - mx) : 0.f;
            sm->e[idx] = e;        // idx < 160 always; pads are zero
            s += e;
        }
        s = wredsum(s);
        if (lane == 0) sm->bf[0] = 1.f / s;
    }

    // warps 8..14: Whh@hc gate sums parked in smem
    if (wib >= 8 && wib < 15) {
        int wp = wib - 8;
        int row = wp * GRID + (int)blockIdx.x;
        if (row < H) {
            const float4* h4 = (const float4*)hc;
            const float4* W0 = (const float4*)(dec_Whh + (size_t)row * H);
            const float4* W1 = (const float4*)(dec_Whh + (size_t)(row + H) * H);
            const float4* W2 = (const float4*)(dec_Whh + (size_t)(row + 2 * H) * H);
            float hr = 0.f, hz = 0.f, hn = 0.f;
#pragma unroll 4
            for (int k = lane; k < H4; k += 32) {
                float4 hv = h4[k];
                hr += dot4(W0[k], hv);
                hz += dot4(W1[k], hv);
                hn += dot4(W2[k], hv);
            }
            hr = wredsum(hr); hz = wredsum(hz); hn = wredsum(hn);
            if (lane == 0) {
                sm->gh[wp][0] = hr + dec_bhh[row];
                sm->gh[wp][1] = hz + dec_bhh[row + H];
                sm->gh[wp][2] = hn + dec_bhh[row + 2 * H];
            }
        }
    }

    int row = wib * GRID + (int)blockIdx.x;
    bool act = (wib < 7) && (row < H);
    float a = 0.f;
    if (act) {
        const float4* W  = (const float4*)(comb_W + (size_t)row * 2 * H);
        const float4* e4 = (const float4*)(dec_emb + (size_t)tok * H);
#pragma unroll 8
        for (int k = lane; k < H4; k += 32) a += dot4(W[k], e4[k]);
    }
    __syncthreads();
    if (act) {
        const float* Mr = g_M + (size_t)row * ATTP;
        float b = 0.f;
#pragma unroll
        for (int k = 0; k < 5; k++) {
            int t = lane + 32 * k;
            b += sm->e[t] * Mr[t];   // pads contribute 0
        }
        float tot = a + b * sm->bf[0];
        tot = wredsum(tot);
        if (lane == 0) g_comb[row] = fmaxf(tot + comb_b[row], 0.f);
    }
}

// decoder phase B: finish GRU — Wih@comb dots + gate math using parked Whh sums.
__device__ __forceinline__ void gru_fin_phase(
    const float* __restrict__ dec_Wih, const float* __restrict__ dec_bih,
    const float* __restrict__ hc, float* __restrict__ hn_out, Smem* sm)
{
    int wib = threadIdx.x >> 5;
    int lane = threadIdx.x & 31;
    if (wib >= 7) return;
    int row = wib * GRID + (int)blockIdx.x;
    if (row >= H) return;

    const float4* x4 = (const float4*)g_comb;
    const float4* W0 = (const float4*)(dec_Wih + (size_t)row * H);
    const float4* W1 = (const float4*)(dec_Wih + (size_t)(row + H) * H);
    const float4* W2 = (const float4*)(dec_Wih + (size_t)(row + 2 * H) * H);
    float ir = 0.f, iz = 0.f, inn = 0.f;
#pragma unroll 4
    for (int k = lane; k < H4; k += 32) {
        float4 xv = x4[k];
        ir  += dot4(W0[k], xv);
        iz  += dot4(W1[k], xv);
        inn += dot4(W2[k], xv);
    }
    ir = wredsum(ir); iz = wredsum(iz); inn = wredsum(inn);
    if (lane == 0) {
        ir  += dec_bih[row];
        iz  += dec_bih[row + H];
        inn += dec_bih[row + 2 * H];
        float hr = sm->gh[wib][0];
        float hz = sm->gh[wib][1];
        float hn = sm->gh[wib][2];
        float r = 1.f / (1.f + expf(-(ir + hr)));
        float z = 1.f / (1.f + expf(-(iz + hz)));
        float n = tanhf(inn + r * hn);
        hn_out[row] = (1.f - z) * n + z * hc[row];
    }
}

// logits GEMV on int8 weights (fully L2-resident) with per-step int8 h.
// logit = dp4a-sum * (w_scale[r] * h_scale) + out_b[r].
__device__ __forceinline__ void logits_phase(
    const float* __restrict__ out_b, const float* __restrict__ h, Smem* sm)
{
    int tid = threadIdx.x, lane = tid & 31, wib = tid >> 5;
    int gw = (int)blockIdx.x * WPB + wib;

    if (tid < WPB * MAXSLOT) sm->slot[tid] = -INFINITY;

    // 1. block maxabs of h
    float m0 = fmaxf(fabsf(h[tid]), fabsf(h[tid + 512]));
    m0 = wredmax(m0);
    if (lane == 0) sm->red[wib] = m0;
    __syncthreads();
    if (tid == 0) {
        float M = sm->red[0];
#pragma unroll
        for (int i = 1; i < WPB; i++) M = fmaxf(M, sm->red[i]);
        sm->bf[1] = M * (1.f / 127.f);            // h_scale
        sm->bf[2] = (M > 0.f) ? (127.f / M) : 0.f;
    }
    __syncthreads();
    float hs   = sm->bf[1];
    float hinv = sm->bf[2];

    // 2. quantize h into smem (4 int8 per uint, element 4t+c -> uint t byte c)
    if (tid < 256) sm->hq[tid] = q4(((const float4*)h)[tid], hinv);
    __syncthreads();

    // 3. hq registers for this lane (uint4 idx lane and lane+32)
    const uint4* hq4 = (const uint4*)sm->hq;
    uint4 hA = hq4[lane];
    uint4 hB = hq4[lane + 32];

    float* slotp = sm->slot + wib * MAXSLOT;

    // 4. two batches of 7 rows (14 uint4 loads in flight per batch)
#pragma unroll
    for (int b = 0; b < 2; b++) {
        int base = b * 7;
        uint4 wA[7], wB[7];
        int rr[7];
        bool okk[7];
#pragma unroll
        for (int j = 0; j < 7; j++) {
            int r = gw + (base + j) * NWARPS;
            okk[j] = (r < VOUT);
            if (!okk[j]) r = gw;
            rr[j] = r;
            const uint4* Wq = (const uint4*)(g_wq + (size_t)r * 256);
            wA[j] = __ldg(&Wq[lane]);
            wB[j] = __ldg(&Wq[lane + 32]);
        }
#pragma unroll
        for (int j = 0; j < 7; j++) {
            int acc = 0;
            acc = __dp4a((int)wA[j].x, (int)hA.x, acc);
            acc = __dp4a((int)wA[j].y, (int)hA.y, acc);
            acc = __dp4a((int)wA[j].z, (int)hA.z, acc);
            acc = __dp4a((int)wA[j].w, (int)hA.w, acc);
            acc = __dp4a((int)wB[j].x, (int)hB.x, acc);
            acc = __dp4a((int)wB[j].y, (int)hB.y, acc);
            acc = __dp4a((int)wB[j].z, (int)hB.z, acc);
            acc = __dp4a((int)wB[j].w, (int)hB.w, acc);
            acc = wredsumi(acc);
            if (lane == 0 && okk[j]) {
                int r = rr[j];
                float lg = (float)acc * (g_wscale[r] * hs) + out_b[r];
                g_logits[r] = lg;
                slotp[base + j] = lg;
            }
        }
    }

    // per-warp top-4 scan (lane0, off the hot loop)
    if (lane == 0) {
        unsigned long long c0 = 0, c1 = 0, c2 = 0, c3 = 0;
#pragma unroll
        for (int n = 0; n < MAXSLOT; n++) {
            int row = gw + n * NWARPS;
            if (row < VOUT) {
                unsigned long long p = packf(slotp[n], row);
                top4_ins(c0, c1, c2, c3, p);
            }
        }
        sm->wtop[wib][0] = c0; sm->wtop[wib][1] = c1;
        sm->wtop[wib][2] = c2; sm->wtop[wib][3] = c3;
    }
    __syncthreads();

    // warp0: pop-merge 16 warp lists -> CTA top-4
    if (wib == 0) {
        unsigned long long a0 = 0, a1 = 0, a2 = 0, a3 = 0;
        if (lane < WPB) {
            a0 = sm->wtop[lane][0]; a1 = sm->wtop[lane][1];
            a2 = sm->wtop[lane][2]; a3 = sm->wtop[lane][3];
        }
        int pos = 0;
        unsigned long long t[4];
#pragma unroll
        for (int k = 0; k < 4; k++) {
            unsigned long long head = (pos == 0) ? a0 : (pos == 1) ? a1 :
                                      (pos == 2) ? a2 : (pos == 3) ? a3 : 0ull;
            unsigned long long m = wredmaxu64(head);
            t[k] = m;
            if (head == m && pos < 4) pos++;
        }
        if (lane == 0) {
#pragma unroll
            for (int k = 0; k < 4; k++) g_ptop[blockIdx.x][k] = t[k];
            sm->bu = t[0];
        }
    }
    __syncthreads();

    // CTA sumexp wrt CTA max: warp-level (slots 0..223 covered by warps 0..6)
    {
        float m = unpack_max(sm->bu);
        float e = (tid < WPB * MAXSLOT) ? expf(sm->slot[tid] - m) : 0.f;
        e = wredsum(e);
        if (lane == 0) sm->red[wib] = e;
        __syncthreads();
        if (tid == 0) {
            float S = 0.f;
#pragma unroll
            for (int i = 0; i < 7; i++) S += sm->red[i];
            g_psum[blockIdx.x] = S;
        }
    }
}

// global top-4 merge + lse; fp32 recheck of top-4 for exact argmax;
// write logp row; fuse next-step attention-logit prep
__device__ __forceinline__ void out_phase(
    float* __restrict__ out, int step,
    const float* __restrict__ out_W, const float* __restrict__ out_b,
    const float* __restrict__ attn_W, const float* __restrict__ attn_b,
    const float* __restrict__ dec_emb, const float* __restrict__ h, Smem* sm)
{
    int tid = threadIdx.x, lane = tid & 31, wib = tid >> 5;

    if (wib == 0) {
        unsigned long long c0 = 0, c1 = 0, c2 = 0, c3 = 0;
        for (int cc = lane; cc < GRID; cc += 32) {
#pragma unroll
            for (int k = 0; k < 4; k++)
                top4_ins(c0, c1, c2, c3, g_ptop[cc][k]);
        }
        int pos = 0;
        unsigned long long t[4];
#pragma unroll
        for (int k = 0; k < 4; k++) {
            unsigned long long head = (pos == 0) ? c0 : (pos == 1) ? c1 :
                                      (pos == 2) ? c2 : (pos == 3) ? c3 : 0ull;
            unsigned long long mm = wredmaxu64(head);
            t[k] = mm;
            if (head == mm && pos < 4) pos++;
        }
        float M = unpack_max(t[0]);
        float S = 0.f;
        for (int cc = lane; cc < GRID; cc += 32)
            S += g_psum[cc] * expf(unpack_max(g_ptop[cc][0]) - M);
        S = wredsum(S);
        if (lane == 0) {
#pragma unroll
            for (int k = 0; k < 4; k++) sm->top4[k] = t[k];
            sm->bf[0] = M + logf(S);
        }
    }
    __syncthreads();
    float lse = sm->bf[0];

    int g = (int)blockIdx.x * BLOCK + tid;
    if (g < VOUT) out[(size_t)step * VOUT + g] = g_logits[g] - lse;

    // fp32 recheck of the 4 candidates (warps 0..3, one row each)
    if (wib < 4) {
        int rk = unpack_idx(sm->top4[wib]);
        const float4* W = (const float4*)(out_W + (size_t)rk * H);
        const float4* h4 = (const float4*)h;
        float a = 0.f;
#pragma unroll 4
        for (int k = lane; k < H4; k += 32) a += dot4(W[k], h4[k]);
        a = wredsum(a);
        if (lane == 0) sm->cand[wib] = packf(a + out_b[rk], rk);
    }
    __syncthreads();
    unsigned long long w = sm->cand[0];
#pragma unroll
    for (int k = 1; k < 4; k++) if (sm->cand[k] > w) w = sm->cand[k];
    int tok = unpack_idx(w);

    // next-step attention logits: two-warp split per CTA row
    if ((int)blockIdx.x < ATT) {
        int r = (int)blockIdx.x;
        if (wib == 8) {        // emb half
            const float4* W  = (const float4*)(attn_W + (size_t)r * 2 * H);
            const float4* e4 = (const float4*)(dec_emb + (size_t)tok * H);
            float a = 0.f;
#pragma unroll 4
            for (int k = lane; k < H4; k += 32) a += dot4(W[k], e4[k]);
            a = wredsum(a);
            if (lane == 0) sm->bf[1] = a;
        } else if (wib == 9) { // h half
            const float4* W  = (const float4*)(attn_W + (size_t)r * 2 * H + H);
            const float4* h4 = (const float4*)h;
            float a = 0.f;
#pragma unroll 4
            for (int k = lane; k < H4; k += 32) a += dot4(W[k], h4[k]);
            a = wredsum(a);
            if (lane == 0) sm->bf[2] = a;
        }
        __syncthreads();
        if (tid == 0) g_attn[r] = sm->bf[1] + sm->bf[2] + attn_b[r];
    }
    if (blockIdx.x == 0 && tid == 0) g_tok = tok;
}

// ---------------- the single persistent kernel ----------------
__global__ void __launch_bounds__(BLOCK, 1) k_all(
    const int* __restrict__ tokens,
    const float* __restrict__ enc_emb,
    const float* __restrict__ enc_Wih, const float* __restrict__ enc_Whh,
    const float* __restrict__ enc_bih, const float* __restrict__ enc_bhh,
    const float* __restrict__ dec_emb,
    const float* __restrict__ attn_W, const float* __restrict__ attn_b,
    const float* __restrict__ comb_W, const float* __restrict__ comb_b,
    const float* __restrict__ dec_Wih, const float* __restrict__ dec_Whh,
    const float* __restrict__ dec_bih, const float* __restrict__ dec_bhh,
    const float* __restrict__ out_W, const float* __restrict__ out_b,
    float* __restrict__ out)
{
    __shared__ Smem sm;
    int tid = threadIdx.x;
    int wib = tid >> 5, lane = tid & 31;

    // one-time: quantize out_W to int8 with per-row scale (warp per row)
    {
        int gw = (int)blockIdx.x * WPB + wib;
#pragma unroll 1
        for (int n = 0; n < MAXSLOT; n++) {
            int r = gw + n * NWARPS;
            if (r >= VOUT) break;
            const float4* wr = (const float4*)(out_W + (size_t)r * H);
            float4 v[8];
            float mx = 0.f;
#pragma unroll
            for (int i = 0; i < 8; i++) {
                v[i] = __ldcs(&wr[lane + 32 * i]);
                mx = fmaxf(mx, fmaxf(fmaxf(fabsf(v[i].x), fabsf(v[i].y)),
                                     fmaxf(fabsf(v[i].z), fabsf(v[i].w))));
            }
            mx = wredmax(mx);
            float inv = (mx > 0.f) ? (127.f / mx) : 0.f;
            unsigned* dst = g_wq + (size_t)r * 256;
#pragma unroll
            for (int i = 0; i < 8; i++)
                dst[lane + 32 * i] = q4(v[i], inv);
            if (lane == 0) g_wscale[r] = mx * (1.f / 127.f);
        }
    }

    // init: h0 = 0, zero enc_T (padding columns must be 0)
    {
        int gt = (int)blockIdx.x * BLOCK + tid;
        if (gt < H) g_h[0][gt] = 0.f;
        for (int i = gt; i < H * ATTP; i += GRID * BLOCK) g_enc_T[i] = 0.f;
    }
    gsync();

    // ---- encoder (warp-pair split, writes transposed enc_T) ----
    for (int t = 0; t < ML; t++) {
        const float* x = enc_emb + (size_t)tokens[t] * H;
        gru_phase_enc(enc_Wih, enc_Whh, enc_bih, enc_bhh, x,
                      g_h[t & 1], g_h[(t & 1) ^ 1], t, &sm);
        gsync();
    }
    // final encoder hidden in g_h[0]

    // ---- build M (warps 0..6) + decoder prep (warps 8,9) in one phase ----
    build_M(comb_W);
    if ((int)blockIdx.x < ATT) {
        int r = (int)blockIdx.x;
        if (wib == 8) {        // emb half (tok = SOS = 0)
            const float4* W  = (const float4*)(attn_W + (size_t)r * 2 * H);
            const float4* e4 = (const float4*)dec_emb;
            float a = 0.f;
#pragma unroll 4
            for (int k = lane; k < H4; k += 32) a += dot4(W[k], e4[k]);
            a = wredsum(a);
            if (lane == 0) sm.bf[1] = a;
        } else if (wib == 9) { // h half
            const float4* W  = (const float4*)(attn_W + (size_t)r * 2 * H + H);
            const float4* h4 = (const float4*)g_h[0];
            float a = 0.f;
#pragma unroll 4
            for (int k = lane; k < H4; k += 32) a += dot4(W[k], h4[k]);
            a = wredsum(a);
            if (lane == 0) sm.bf[2] = a;
        }
    }
    __syncthreads();
    if ((int)blockIdx.x < ATT && tid == 0)
        g_attn[blockIdx.x] = sm.bf[1] + sm.bf[2] + attn_b[blockIdx.x];
    if (blockIdx.x == 0 && tid == 0) g_tok = 0;
    gsync();

    // ---- decoder: 4 barriers per step ----
    for (int s = 0; s < ML; s++) {
        const float* hc = g_h[s & 1];
        float* hn = g_h[(s & 1) ^ 1];

        comb_whh_phase(comb_W, comb_b, dec_emb,
                       dec_Whh, dec_bhh, hc, &sm);             gsync();
        gru_fin_phase(dec_Wih, dec_bih, hc, hn, &sm);          gsync();
        logits_phase(out_b, hn, &sm);                          gsync();
        out_phase(out, s, out_W, out_b, attn_W, attn_b,
                  dec_emb, hn, &sm);                           gsync();
    }
}

// ---------------- host launcher ----------------
extern "C" void kernel_launch(void* const* d_in, const int* in_sizes, int n_in,
                              void* d_out, int out_size)
{
    const int*   tokens  = (const int*)  d_in[0];
    // d_in[1] = max_length (compile-time ML=128)
    const float* enc_emb = (const float*)d_in[2];
    const float* enc_Wih = (const float*)d_in[3];
    const float* enc_Whh = (const float*)d_in[4];
    const float* enc_bih = (const float*)d_in[5];
    const float* enc_bhh = (const float*)d_in[6];
    const float* dec_emb = (const float*)d_in[7];
    const float* attn_W  = (const float*)d_in[8];
    const float* attn_b  = (const float*)d_in[9];
    const float* comb_W  = (const float*)d_in[10];
    const float* comb_b  = (const float*)d_in[11];
    const float* dec_Wih = (const float*)d_in[12];
    const float* dec_Whh = (const float*)d_in[13];
    const float* dec_bih = (const float*)d_in[14];
    const float* dec_bhh = (const float*)d_in[15];
    const float* out_W   = (const float*)d_in[16];
    const float* out_b   = (const float*)d_in[17];
    float* out = (float*)d_out;

    k_all<<<GRID, BLOCK>>>(tokens, enc_emb, enc_Wih, enc_Whh, enc_bih, enc_bhh,
                           dec_emb, attn_W, attn_b, comb_W, comb_b,
                           dec_Wih, dec_Whh, dec_bih, dec_bhh,
                           out_W, out_b, out);
}

// round 14
// speedup vs baseline: 1.2227x; 1.0283x over previous
#include <cuda_runtime.h>
#include <cuda_bf16.h>
#include <math.h>

#define H      1024
#define H4     256          // H/4
#define VOUT   32000
#define ML     128
#define ATT    129          // ML + 1
#define ATTP   160          // padded attention length (multiple of 32)
#define GRID   148
#define BLOCK  512
#define WPB    (BLOCK/32)   // 16 warps per block
#define NWARPS (GRID*WPB)   // 2368
#define MAXSLOT 14          // max rows per warp

// ---------------- device scratch (static, no allocation) ----------------
__device__ float g_h[2][H];
__device__ float g_enc_T[(size_t)H * ATTP];    // transposed encoder outputs [j][t]
__device__ float g_M[(size_t)H * ATTP];        // M[i][t] = dot(W2[i], enc_out[t])
__device__ float g_attn[ATT];
__device__ float g_comb[H];
__device__ float g_logits[VOUT];
__device__ unsigned long long g_ptop[GRID][4]; // per-CTA top-4 packed
__device__ float g_psum[GRID];                 // per-CTA sumexp wrt its own max
__device__ unsigned g_wq[(size_t)VOUT * 256];  // 32MB int8 out_W (4 int8 / uint)
__device__ float g_wscale[VOUT];               // per-row dequant scale (maxabs/127)

__device__ unsigned g_bar_count = 0;
__device__ unsigned g_bar_gen   = 0;

// ---------------- helpers ----------------
__device__ __forceinline__ float wredsum(float v) {
#pragma unroll
    for (int o = 16; o > 0; o >>= 1) v += __shfl_xor_sync(0xffffffffu, v, o);
    return v;
}
__device__ __forceinline__ int wredsumi(int v) {
#pragma unroll
    for (int o = 16; o > 0; o >>= 1) v += __shfl_xor_sync(0xffffffffu, v, o);
    return v;
}
__device__ __forceinline__ float wredmax(float v) {
#pragma unroll
    for (int o = 16; o > 0; o >>= 1) v = fmaxf(v, __shfl_xor_sync(0xffffffffu, v, o));
    return v;
}
__device__ __forceinline__ unsigned long long wredmaxu64(unsigned long long v) {
#pragma unroll
    for (int o = 16; o > 0; o >>= 1) {
        unsigned long long q = __shfl_xor_sync(0xffffffffu, v, o);
        if (q > v) v = q;
    }
    return v;
}

__device__ __forceinline__ unsigned long long packf(float v, int idx) {
    unsigned u = __float_as_uint(v);
    u = (u & 0x80000000u) ? ~u : (u | 0x80000000u);   // totally ordered float bits
    return ((unsigned long long)u << 32) | (unsigned)(~(unsigned)idx); // tie -> lowest idx
}
__device__ __forceinline__ float unpack_max(unsigned long long p) {
    unsigned u = (unsigned)(p >> 32);
    unsigned b = (u & 0x80000000u) ? (u & 0x7fffffffu) : ~u;
    return __uint_as_float(b);
}
__device__ __forceinline__ int unpack_idx(unsigned long long p) {
    return (int)(~(unsigned)(p & 0xffffffffu));
}

__device__ __forceinline__ float dot4(float4 a, float4 b) {
    return a.x * b.x + a.y * b.y + a.z * b.z + a.w * b.w;
}

__device__ __forceinline__ unsigned q4(float4 v, float inv) {
    int a = __float2int_rn(v.x * inv);
    int b = __float2int_rn(v.y * inv);
    int c = __float2int_rn(v.z * inv);
    int d = __float2int_rn(v.w * inv);
    return (unsigned)(a & 0xFF) | ((unsigned)(b & 0xFF) << 8) |
           ((unsigned)(c & 0xFF) << 16) | ((unsigned)(d & 0xFF) << 24);
}

// insert p into descending top-4
__device__ __forceinline__ void top4_ins(unsigned long long& c0, unsigned long long& c1,
                                         unsigned long long& c2, unsigned long long& c3,
                                         unsigned long long p) {
    if (p > c0)      { c3 = c2; c2 = c1; c1 = c0; c0 = p; }
    else if (p > c1) { c3 = c2; c2 = c1; c1 = p; }
    else if (p > c2) { c3 = c2; c2 = p; }
    else if (p > c3) { c3 = p; }
}

// ---------------- grid-wide barrier ----------------
__device__ __forceinline__ unsigned ld_acq(unsigned* p) {
    unsigned v;
    asm volatile("ld.acquire.gpu.u32 %0, [%1];" : "=r"(v) : "l"(p) : "memory");
    return v;
}
__device__ __forceinline__ void st_rel(unsigned* p, unsigned v) {
    asm volatile("st.release.gpu.u32 [%0], %1;" :: "l"(p), "r"(v) : "memory");
}

__device__ __forceinline__ void gsync() {
    __syncthreads();
    if (threadIdx.x == 0) {
        unsigned gen = ld_acq(&g_bar_gen);
        __threadfence();
        if (atomicAdd(&g_bar_count, 1) == GRID - 1) {
            g_bar_count = 0;
            st_rel(&g_bar_gen, gen + 1);
        } else {
            while (ld_acq(&g_bar_gen) == gen) { }
        }
    }
    __syncthreads();
}

#define BAR6() asm volatile("bar.sync 1, 192;" ::: "memory")

// ---------------- shared-memory layout ----------------
struct Smem {
    float e[ATTP];                // attention softmax weights (zero-padded)
    float slot[WPB * MAXSLOT];    // raw logits per warp slot
    float red[WPB];               // warp-level reduction scratch
    float gh[8][4];               // Whh@h gate sums (+bhh), from prev D / prep
    float gi[8][4];               // Wih@comb high-half partials (B exchange)
    float ca[8];                  // comb high-half partials (A exchange)
    unsigned hq[256];             // quantized h (4 int8 per uint)
    unsigned long long wtop[WPB][4];
    unsigned long long top4[4];
    unsigned long long cand[4];
    float bf[4];                  // scalar broadcasts (bf[3] = lse for delayed write)
    unsigned long long bu;
    int tk;                       // CTA-local current token
};

// ---------------- phases ----------------

// Encoder GRU step (unchanged from R13)
__device__ __forceinline__ void gru_phase_enc(
    const float* __restrict__ Wih, const float* __restrict__ Whh,
    const float* __restrict__ bih, const float* __restrict__ bhh,
    const float* __restrict__ x, const float* __restrict__ h,
    float* __restrict__ ho, int t, Smem* sm)
{
    int wib = threadIdx.x >> 5;
    int lane = threadIdx.x & 31;
    int wp = wib & 7;
    bool xs = (wib < 7);
    bool hs = (wib >= 8 && wib < 15);
    int row = wp * GRID + (int)blockIdx.x;
    bool act = (xs || hs) && row < H;

    float a0 = 0.f, a1 = 0.f, a2 = 0.f;
    if (act) {
        const float*  W  = xs ? Wih : Whh;
        const float4* v4 = (const float4*)(xs ? x : h);
        const float4* W0 = (const float4*)(W + (size_t)row * H);
        const float4* W1 = (const float4*)(W + (size_t)(row + H) * H);
        const float4* W2 = (const float4*)(W + (size_t)(row + 2 * H) * H);
#pragma unroll 4
        for (int k = lane; k < H4; k += 32) {
            float4 vv = v4[k];
            a0 += dot4(W0[k], vv);
            a1 += dot4(W1[k], vv);
            a2 += dot4(W2[k], vv);
        }
        a0 = wredsum(a0); a1 = wredsum(a1); a2 = wredsum(a2);
        if (hs && lane == 0) {
            sm->gh[wp][0] = a0 + bhh[row];
            sm->gh[wp][1] = a1 + bhh[row + H];
            sm->gh[wp][2] = a2 + bhh[row + 2 * H];
        }
    }
    __syncthreads();
    if (act && xs && lane == 0) {
        float ir  = a0 + bih[row];
        float iz  = a1 + bih[row + H];
        float inn = a2 + bih[row + 2 * H];
        float hr = sm->gh[wp][0];
        float hz = sm->gh[wp][1];
        float hn = sm->gh[wp][2];
        float r = 1.f / (1.f + expf(-(ir + hr)));
        float z = 1.f / (1.f + expf(-(iz + hz)));
        float n = tanhf(inn + r * hn);
        float hnew = (1.f - z) * n + z * h[row];
        ho[row] = hnew;
        g_enc_T[(size_t)row * ATTP + t] = hnew;
    }
}

// one-time after encoder: M[i][t] = dot(comb_W[i, H:2H], enc_out[t])
__device__ __forceinline__ void build_M(const float* __restrict__ comb_W)
{
    int wib = threadIdx.x >> 5;
    int lane = threadIdx.x & 31;
    if (wib >= 7) return;
    int row = wib * GRID + (int)blockIdx.x;
    if (row >= H) return;

    const float4* W2 = (const float4*)(comb_W + (size_t)row * 2 * H + H);
    float a0 = 0.f, a1 = 0.f, a2 = 0.f, a3 = 0.f, a4 = 0.f;
#pragma unroll 2
    for (int j4 = 0; j4 < H4; j4++) {
        float4 w = W2[j4];
        const float* E = g_enc_T + (size_t)(j4 * 4) * ATTP + lane;
#pragma unroll
        for (int c = 0; c < 4; c++) {
            float wc = (c == 0) ? w.x : (c == 1) ? w.y : (c == 2) ? w.z : w.w;
            const float* Ec = E + (size_t)c * ATTP;
            a0 += wc * Ec[0];
            a1 += wc * Ec[32];
            a2 += wc * Ec[64];
            a3 += wc * Ec[96];
            a4 += wc * Ec[128];
        }
    }
    float* Mr = g_M + (size_t)row * ATTP;
    Mr[lane]       = a0;
    Mr[lane + 32]  = a1;
    Mr[lane + 64]  = a2;
    Mr[lane + 96]  = a3;
    Mr[lane + 128] = a4;
}

// Whh@h gate sums for all 7 rows of this CTA, arbitrary 7-warp set.
// wp in [0,7), writes sm->gh[wp] (+bhh).
__device__ __forceinline__ void whh_dots(
    const float* __restrict__ Whh, const float* __restrict__ bhh,
    const float* __restrict__ h, int wp, int lane, Smem* sm)
{
    int row = wp * GRID + (int)blockIdx.x;
    if (row >= H) return;
    const float4* h4 = (const float4*)h;
    const float4* W0 = (const float4*)(Whh + (size_t)row * H);
    const float4* W1 = (const float4*)(Whh + (size_t)(row + H) * H);
    const float4* W2 = (const float4*)(Whh + (size_t)(row + 2 * H) * H);
    float hr = 0.f, hz = 0.f, hn = 0.f;
#pragma unroll 4
    for (int k = lane; k < H4; k += 32) {
        float4 hv = h4[k];
        hr += dot4(W0[k], hv);
        hz += dot4(W1[k], hv);
        hn += dot4(W2[k], hv);
    }
    hr = wredsum(hr); hz = wredsum(hz); hn = wredsum(hn);
    if (lane == 0) {
        sm->gh[wp][0] = hr + bhh[row];
        sm->gh[wp][1] = hz + bhh[row + H];
        sm->gh[wp][2] = hn + bhh[row + 2 * H];
    }
}

// Phase A: softmax (w15) + comb rows k-split across warp pairs (w0-6 / w8-14).
__device__ __forceinline__ void comb_phase(
    const float* __restrict__ comb_W, const float* __restrict__ comb_b,
    const float* __restrict__ dec_emb, Smem* sm)
{
    int wib = threadIdx.x >> 5;
    int lane = threadIdx.x & 31;
    int tok = sm->tk;

    if (wib == 15) {   // local softmax of the 129 attention logits
        float v[5];
        float mx = -INFINITY;
#pragma unroll
        for (int k = 0; k < 5; k++) {
            int idx = lane + 32 * k;
            v[k] = (idx < ATT) ? g_attn[idx] : -INFINITY;
            mx = fmaxf(mx, v[k]);
        }
        mx = wredmax(mx);
        float s = 0.f;
#pragma unroll
        for (int k = 0; k < 5; k++) {
            int idx = lane + 32 * k;
            float e = (idx < ATT) ? expf(v[k] - mx) : 0.f;
            sm->e[idx] = e;
            s += e;
        }
        s = wredsum(s);
        if (lane == 0) sm->bf[0] = 1.f / s;
    }

    int wp = wib & 7;
    bool lo = (wib < 7);
    bool hi = (wib >= 8 && wib < 15);
    int row = wp * GRID + (int)blockIdx.x;
    bool act = (lo || hi) && row < H;

    float a = 0.f;
    if (act) {
        const float4* W  = (const float4*)(comb_W + (size_t)row * 2 * H);
        const float4* e4 = (const float4*)(dec_emb + (size_t)tok * H);
        int k0 = lo ? 0 : 128;
#pragma unroll 4
        for (int k = k0 + lane; k < k0 + 128; k += 32) a += dot4(W[k], e4[k]);
        if (hi) {
            a = wredsum(a);
            if (lane == 0) sm->ca[wp] = a;
        }
    }
    __syncthreads();
    if (act && lo) {
        const float* Mr = g_M + (size_t)row * ATTP;
        float b = 0.f;
#pragma unroll
        for (int k = 0; k < 5; k++) {
            int t = lane + 32 * k;
            b += sm->e[t] * Mr[t];
        }
        float tot = a + b * sm->bf[0];
        tot = wredsum(tot);
        if (lane == 0)
            g_comb[row] = fmaxf(tot + sm->ca[wp] + comb_b[row], 0.f);
    }
}

// Phase B: gru finish — Wih@comb k-split (w0-6 low / w8-14 high) + gates from
// parked Whh sums; warps 7,15 write the PREVIOUS step's output row.
__device__ __forceinline__ void gru_fin_phase(
    const float* __restrict__ dec_Wih, const float* __restrict__ dec_bih,
    const float* __restrict__ hc, float* __restrict__ hn_out,
    float* __restrict__ out, int step, Smem* sm)
{
    int wib = threadIdx.x >> 5;
    int lane = threadIdx.x & 31;
    int wp = wib & 7;
    bool lo = (wib < 7);
    bool hi = (wib >= 8 && wib < 15);
    int row = wp * GRID + (int)blockIdx.x;
    bool act = (lo || hi) && row < H;

    float ir = 0.f, iz = 0.f, inn = 0.f;
    if (act) {
        const float4* x4 = (const float4*)g_comb;
        const float4* W0 = (const float4*)(dec_Wih + (size_t)row * H);
        const float4* W1 = (const float4*)(dec_Wih + (size_t)(row + H) * H);
        const float4* W2 = (const float4*)(dec_Wih + (size_t)(row + 2 * H) * H);
        int k0 = lo ? 0 : 128;
#pragma unroll 4
        for (int k = k0 + lane; k < k0 + 128; k += 32) {
            float4 xv = x4[k];
            ir  += dot4(W0[k], xv);
            iz  += dot4(W1[k], xv);
            inn += dot4(W2[k], xv);
        }
        ir = wredsum(ir); iz = wredsum(iz); inn = wredsum(inn);
        if (hi && lane == 0) {
            sm->gi[wp][0] = ir; sm->gi[wp][1] = iz; sm->gi[wp][2] = inn;
        }
    } else if ((wib == 7 || wib == 15) && step > 0) {
        float lse = sm->bf[3];
        int wt = (wib == 7 ? lane : 32 + lane);
        for (int g = (int)blockIdx.x * 64 + wt; g < VOUT; g += GRID * 64)
            out[(size_t)(step - 1) * VOUT + g] = g_logits[g] - lse;
    }
    __syncthreads();
    if (act && lo && lane == 0) {
        float IR = ir + sm->gi[wp][0] + dec_bih[row];
        float IZ = iz + sm->gi[wp][1] + dec_bih[row + H];
        float IN = inn + sm->gi[wp][2] + dec_bih[row + 2 * H];
        float hr = sm->gh[wp][0];
        float hz = sm->gh[wp][1];
        float hn = sm->gh[wp][2];
        float r = 1.f / (1.f + expf(-(IR + hr)));
        float z = 1.f / (1.f + expf(-(IZ + hz)));
        float n = tanhf(IN + r * hn);
        hn_out[row] = (1.f - z) * n + z * hc[row];
    }
}

// Phase C: logits GEMV on int8 weights (unchanged from R13)
__device__ __forceinline__ void logits_phase(
    const float* __restrict__ out_b, const float* __restrict__ h, Smem* sm)
{
    int tid = threadIdx.x, lane = tid & 31, wib = tid >> 5;
    int gw = (int)blockIdx.x * WPB + wib;

    if (tid < WPB * MAXSLOT) sm->slot[tid] = -INFINITY;

    float m0 = fmaxf(fabsf(h[tid]), fabsf(h[tid + 512]));
    m0 = wredmax(m0);
    if (lane == 0) sm->red[wib] = m0;
    __syncthreads();
    if (tid == 0) {
        float M = sm->red[0];
#pragma unroll
        for (int i = 1; i < WPB; i++) M = fmaxf(M, sm->red[i]);
        sm->bf[1] = M * (1.f / 127.f);
        sm->bf[2] = (M > 0.f) ? (127.f / M) : 0.f;
    }
    __syncthreads();
    float hs   = sm->bf[1];
    float hinv = sm->bf[2];

    if (tid < 256) sm->hq[tid] = q4(((const float4*)h)[tid], hinv);
    __syncthreads();

    const uint4* hq4 = (const uint4*)sm->hq;
    uint4 hA = hq4[lane];
    uint4 hB = hq4[lane + 32];

    float* slotp = sm->slot + wib * MAXSLOT;

#pragma unroll
    for (int b = 0; b < 2; b++) {
        int base = b * 7;
        uint4 wA[7], wB[7];
        int rr[7];
        bool okk[7];
#pragma unroll
        for (int j = 0; j < 7; j++) {
            int r = gw + (base + j) * NWARPS;
            okk[j] = (r < VOUT);
            if (!okk[j]) r = gw;
            rr[j] = r;
            const uint4* Wq = (const uint4*)(g_wq + (size_t)r * 256);
            wA[j] = __ldg(&Wq[lane]);
            wB[j] = __ldg(&Wq[lane + 32]);
        }
#pragma unroll
        for (int j = 0; j < 7; j++) {
            int acc = 0;
            acc = __dp4a((int)wA[j].x, (int)hA.x, acc);
            acc = __dp4a((int)wA[j].y, (int)hA.y, acc);
            acc = __dp4a((int)wA[j].z, (int)hA.z, acc);
            acc = __dp4a((int)wA[j].w, (int)hA.w, acc);
            acc = __dp4a((int)wB[j].x, (int)hB.x, acc);
            acc = __dp4a((int)wB[j].y, (int)hB.y, acc);
            acc = __dp4a((int)wB[j].z, (int)hB.z, acc);
            acc = __dp4a((int)wB[j].w, (int)hB.w, acc);
            acc = wredsumi(acc);
            if (lane == 0 && okk[j]) {
                int r = rr[j];
                float lg = (float)acc * (g_wscale[r] * hs) + out_b[r];
                g_logits[r] = lg;
                slotp[base + j] = lg;
            }
        }
    }

    if (lane == 0) {
        unsigned long long c0 = 0, c1 = 0, c2 = 0, c3 = 0;
#pragma unroll
        for (int n = 0; n < MAXSLOT; n++) {
            int row = gw + n * NWARPS;
            if (row < VOUT) {
                unsigned long long p = packf(slotp[n], row);
                top4_ins(c0, c1, c2, c3, p);
            }
        }
        sm->wtop[wib][0] = c0; sm->wtop[wib][1] = c1;
        sm->wtop[wib][2] = c2; sm->wtop[wib][3] = c3;
    }
    __syncthreads();

    if (wib == 0) {
        unsigned long long a0 = 0, a1 = 0, a2 = 0, a3 = 0;
        if (lane < WPB) {
            a0 = sm->wtop[lane][0]; a1 = sm->wtop[lane][1];
            a2 = sm->wtop[lane][2]; a3 = sm->wtop[lane][3];
        }
        int pos = 0;
        unsigned long long t[4];
#pragma unroll
        for (int k = 0; k < 4; k++) {
            unsigned long long head = (pos == 0) ? a0 : (pos == 1) ? a1 :
                                      (pos == 2) ? a2 : (pos == 3) ? a3 : 0ull;
            unsigned long long m = wredmaxu64(head);
            t[k] = m;
            if (head == m && pos < 4) pos++;
        }
        if (lane == 0) {
#pragma unroll
            for (int k = 0; k < 4; k++) g_ptop[blockIdx.x][k] = t[k];
            sm->bu = t[0];
        }
    }
    __syncthreads();

    {
        float m = unpack_max(sm->bu);
        float e = (tid < WPB * MAXSLOT) ? expf(sm->slot[tid] - m) : 0.f;
        e = wredsum(e);
        if (lane == 0) sm->red[wib] = e;
        __syncthreads();
        if (tid == 0) {
            float S = 0.f;
#pragma unroll
            for (int i = 0; i < 7; i++) S += sm->red[i];
            g_psum[blockIdx.x] = S;
        }
    }
}

// Phase D: warps 0-5 (named barrier): merge + recheck + tok + attn;
// warps 6-12: Whh@hn for NEXT step. No output write (deferred to next B).
__device__ __forceinline__ void out_phase(
    const float* __restrict__ out_W, const float* __restrict__ out_b,
    const float* __restrict__ attn_W, const float* __restrict__ attn_b,
    const float* __restrict__ dec_emb, const float* __restrict__ h,
    const float* __restrict__ dec_Whh, const float* __restrict__ dec_bhh,
    Smem* sm)
{
    int tid = threadIdx.x, lane = tid & 31, wib = tid >> 5;

    if (wib >= 6 && wib < 13) {
        whh_dots(dec_Whh, dec_bhh, h, wib - 6, lane, sm);
        return;                 // (warps 13-15 also just fall through below)
    }
    if (wib >= 13) return;

    // ---- warps 0-5 under named barrier (192 threads) ----
    if (wib == 0) {
        unsigned long long c0 = 0, c1 = 0, c2 = 0, c3 = 0;
        for (int cc = lane; cc < GRID; cc += 32) {
#pragma unroll
            for (int k = 0; k < 4; k++)
                top4_ins(c0, c1, c2, c3, g_ptop[cc][k]);
        }
        int pos = 0;
        unsigned long long t[4];
#pragma unroll
        for (int k = 0; k < 4; k++) {
            unsigned long long head = (pos == 0) ? c0 : (pos == 1) ? c1 :
                                      (pos == 2) ? c2 : (pos == 3) ? c3 : 0ull;
            unsigned long long mm = wredmaxu64(head);
            t[k] = mm;
            if (head == mm && pos < 4) pos++;
        }
        float M = unpack_max(t[0]);
        float S = 0.f;
        for (int cc = lane; cc < GRID; cc += 32)
            S += g_psum[cc] * expf(unpack_max(g_ptop[cc][0]) - M);
        S = wredsum(S);
        if (lane == 0) {
#pragma unroll
            for (int k = 0; k < 4; k++) sm->top4[k] = t[k];
            sm->bf[3] = M + logf(S);      // lse for the deferred write
        }
    }
    BAR6();
    if (wib < 4) {                          // fp32 recheck of 4 candidates
        int rk = unpack_idx(sm->top4[wib]);
        const float4* W = (const float4*)(out_W + (size_t)rk * H);
        const float4* h4 = (const float4*)h;
        float a = 0.f;
#pragma unroll 4
        for (int k = lane; k < H4; k += 32) a += dot4(W[k], h4[k]);
        a = wredsum(a);
        if (lane == 0) sm->cand[wib] = packf(a + out_b[rk], rk);
    }
    BAR6();
    unsigned long long w = sm->cand[0];
#pragma unroll
    for (int k = 1; k < 4; k++) if (sm->cand[k] > w) w = sm->cand[k];
    int tok = unpack_idx(w);
    if (wib == 0 && lane == 0) sm->tk = tok;

    if ((int)blockIdx.x < ATT) {
        int r = (int)blockIdx.x;
        if (wib == 4) {        // emb half
            const float4* W  = (const float4*)(attn_W + (size_t)r * 2 * H);
            const float4* e4 = (const float4*)(dec_emb + (size_t)tok * H);
            float a = 0.f;
#pragma unroll 4
            for (int k = lane; k < H4; k += 32) a += dot4(W[k], e4[k]);
            a = wredsum(a);
            if (lane == 0) sm->bf[1] = a;
        } else if (wib == 5) { // h half
            const float4* W  = (const float4*)(attn_W + (size_t)r * 2 * H + H);
            const float4* h4 = (const float4*)h;
            float a = 0.f;
#pragma unroll 4
            for (int k = lane; k < H4; k += 32) a += dot4(W[k], h4[k]);
            a = wredsum(a);
            if (lane == 0) sm->bf[2] = a;
        }
    }
    BAR6();
    if (wib == 4 && lane == 0 && (int)blockIdx.x < ATT)
        g_attn[blockIdx.x] = sm->bf[1] + sm->bf[2] + attn_b[blockIdx.x];
}

// ---------------- the single persistent kernel ----------------
__global__ void __launch_bounds__(BLOCK, 1) k_all(
    const int* __restrict__ tokens,
    const float* __restrict__ enc_emb,
    const float* __restrict__ enc_Wih, const float* __restrict__ enc_Whh,
    const float* __restrict__ enc_bih, const float* __restrict__ enc_bhh,
    const float* __restrict__ dec_emb,
    const float* __restrict__ attn_W, const float* __restrict__ attn_b,
    const float* __restrict__ comb_W, const float* __restrict__ comb_b,
    const float* __restrict__ dec_Wih, const float* __restrict__ dec_Whh,
    const float* __restrict__ dec_bih, const float* __restrict__ dec_bhh,
    const float* __restrict__ out_W, const float* __restrict__ out_b,
    float* __restrict__ out)
{
    __shared__ Smem sm;
    int tid = threadIdx.x;
    int wib = tid >> 5, lane = tid & 31;

    // one-time: quantize out_W to int8 with per-row scale (warp per row)
    {
        int gw = (int)blockIdx.x * WPB + wib;
#pragma unroll 1
        for (int n = 0; n < MAXSLOT; n++) {
            int r = gw + n * NWARPS;
            if (r >= VOUT) break;
            const float4* wr = (const float4*)(out_W + (size_t)r * H);
            float4 v[8];
            float mx = 0.f;
#pragma unroll
            for (int i = 0; i < 8; i++) {
                v[i] = __ldcs(&wr[lane + 32 * i]);
                mx = fmaxf(mx, fmaxf(fmaxf(fabsf(v[i].x), fabsf(v[i].y)),
                                     fmaxf(fabsf(v[i].z), fabsf(v[i].w))));
            }
            mx = wredmax(mx);
            float inv = (mx > 0.f) ? (127.f / mx) : 0.f;
            unsigned* dst = g_wq + (size_t)r * 256;
#pragma unroll
            for (int i = 0; i < 8; i++)
                dst[lane + 32 * i] = q4(v[i], inv);
            if (lane == 0) g_wscale[r] = mx * (1.f / 127.f);
        }
    }

    // init: h0 = 0, zero enc_T (padding columns must be 0)
    {
        int gt = (int)blockIdx.x * BLOCK + tid;
        if (gt < H) g_h[0][gt] = 0.f;
        for (int i = gt; i < H * ATTP; i += GRID * BLOCK) g_enc_T[i] = 0.f;
    }
    gsync();

    // ---- encoder ----
    for (int t = 0; t < ML; t++) {
        const float* x = enc_emb + (size_t)tokens[t] * H;
        gru_phase_enc(enc_Wih, enc_Whh, enc_bih, enc_bhh, x,
                      g_h[t & 1], g_h[(t & 1) ^ 1], t, &sm);
        gsync();
    }
    // final encoder hidden in g_h[0]

    // ---- prep phase: build M (w0-6) + attn logits (w8,9) + Whh@h0 (w7,10-15) ----
    build_M(comb_W);
    if (wib == 7) whh_dots(dec_Whh, dec_bhh, g_h[0], 6, lane, &sm);
    else if (wib >= 10) whh_dots(dec_Whh, dec_bhh, g_h[0], wib - 10, lane, &sm);
    if ((int)blockIdx.x < ATT) {
        int r = (int)blockIdx.x;
        if (wib == 8) {        // emb half (tok = SOS = 0)
            const float4* W  = (const float4*)(attn_W + (size_t)r * 2 * H);
            const float4* e4 = (const float4*)dec_emb;
            float a = 0.f;
#pragma unroll 4
            for (int k = lane; k < H4; k += 32) a += dot4(W[k], e4[k]);
            a = wredsum(a);
            if (lane == 0) sm.bf[1] = a;
        } else if (wib == 9) { // h half
            const float4* W  = (const float4*)(attn_W + (size_t)r * 2 * H + H);
            const float4* h4 = (const float4*)g_h[0];
            float a = 0.f;
#pragma unroll 4
            for (int k = lane; k < H4; k += 32) a += dot4(W[k], h4[k]);
            a = wredsum(a);
            if (lane == 0) sm.bf[2] = a;
        }
    }
    __syncthreads();
    if ((int)blockIdx.x < ATT && tid == 0)
        g_attn[blockIdx.x] = sm.bf[1] + sm.bf[2] + attn_b[blockIdx.x];
    if (tid == 0) sm.tk = 0;
    gsync();

    // ---- decoder: 4 barriers per step, rebalanced phases ----
    for (int s = 0; s < ML; s++) {
        const float* hc = g_h[s & 1];
        float* hn = g_h[(s & 1) ^ 1];

        comb_phase(comb_W, comb_b, dec_emb, &sm);              gsync();
        gru_fin_phase(dec_Wih, dec_bih, hc, hn, out, s, &sm);  gsync();
        logits_phase(out_b, hn, &sm);                          gsync();
        out_phase(out_W, out_b, attn_W, attn_b, dec_emb, hn,
                  dec_Whh, dec_bhh, &sm);                      gsync();
    }

    // final step's output (lse from last D, g_logits stable)
    {
        float lse = sm.bf[3];
        int g = (int)blockIdx.x * BLOCK + tid;
        if (g < VOUT) out[(size_t)(ML - 1) * VOUT + g] = g_logits[g] - lse;
    }
}

// ---------------- host launcher ----------------
extern "C" void kernel_launch(void* const* d_in, const int* in_sizes, int n_in,
                              void* d_out, int out_size)
{
    const int*   tokens  = (const int*)  d_in[0];
    // d_in[1] = max_length (compile-time ML=128)
    const float* enc_emb = (const float*)d_in[2];
    const float* enc_Wih = (const float*)d_in[3];
    const float* enc_Whh = (const float*)d_in[4];
    const float* enc_bih = (const float*)d_in[5];
    const float* enc_bhh = (const float*)d_in[6];
    const float* dec_emb = (const float*)d_in[7];
    const float* attn_W  = (const float*)d_in[8];
    const float* attn_b  = (const float*)d_in[9];
    const float* comb_W  = (const float*)d_in[10];
    const float* comb_b  = (const float*)d_in[11];
    const float* dec_Wih = (const float*)d_in[12];
    const float* dec_Whh = (const float*)d_in[13];
    const float* dec_bih = (const float*)d_in[14];
    const float* dec_bhh = (const float*)d_in[15];
    const float* out_W   = (const float*)d_in[16];
    const float* out_b   = (const float*)d_in[17];
    float* out = (float*)d_out;

    k_all<<<GRID, BLOCK>>>(tokens, enc_emb, enc_Wih, enc_Whh, enc_bih, enc_bhh,
                           dec_emb, attn_W, attn_b, comb_W, comb_b,
                           dec_Wih, dec_Whh, dec_bih, dec_bhh,
                           out_W, out_b, out);
}